// round 7
// baseline (speedup 1.0000x reference)
#include <cuda_runtime.h>
#include <cuda_fp16.h>
#include <cstdint>

// ---------------- problem constants ----------------
#define K_DIM       2048
#define N_DIM       1024
#define ROWS_WHOLE  8192
#define ROWS_PARTS  32768
#define ROWS_TOTAL  40960

// ---------------- tile / split config ----------------
#define BM 128
#define BN 128
#define BK 16
#define K_T       1216             // K handled by tensor (fp16-split) warps
#define NCHUNK_T  76               // K_T / 16
#define KF_BASE   1216
#define NF        52               // (2048-1216)/16 FFMA chunks

// tensor-side SMEM stage (fp16 splits), stride 24 halves
#define SH 24
#define TERM_H   (BM * SH)
#define AH0_B    0
#define AH1_B    (TERM_H * 2)
#define BH0_B    (2 * TERM_H * 2)
#define BH1_B    (3 * TERM_H * 2)
#define STAGE_B  (4 * TERM_H * 2)      // 24576 bytes

// FFMA-side SMEM
#define AS_B        49152              // 2 stages x 10240 B  (128 x 20 floats)
#define AS_STRIDE_F 20
#define AS_STAGE_F  2560
#define BS_B        69632              // 2 stages x 8448 B   (16 x 132 floats)
#define BS_STRIDE_F 132
#define BS_STAGE_F  2112
#define CS_B        86528              // 128 x 133 floats = 68096 B
#define CS_STRIDE_F 133
#define BIAS_B      154624
#define SMEM_BYTES  155136

typedef unsigned long long u64;

__device__ float g_sumsq[ROWS_TOTAL];

// ---------------- helpers ----------------
__device__ __forceinline__ void mma16(float* c,
                                      uint32_t a0, uint32_t a1, uint32_t a2, uint32_t a3,
                                      uint32_t b0, uint32_t b1) {
    asm volatile(
        "mma.sync.aligned.m16n8k16.row.col.f32.f16.f16.f32 "
        "{%0,%1,%2,%3}, {%4,%5,%6,%7}, {%8,%9}, {%0,%1,%2,%3};"
        : "+f"(c[0]), "+f"(c[1]), "+f"(c[2]), "+f"(c[3])
        : "r"(a0), "r"(a1), "r"(a2), "r"(a3), "r"(b0), "r"(b1));
}
__device__ __forceinline__ u64 ffma2(u64 a, u64 b, u64 c) {
    u64 d;
    asm("fma.rn.f32x2 %0, %1, %2, %3;" : "=l"(d) : "l"(a), "l"(b), "l"(c));
    return d;
}
__device__ __forceinline__ u64 pack2(float lo, float hi) {
    u64 v;
    asm("mov.b64 %0, {%1, %2};" : "=l"(v) : "f"(lo), "f"(hi));
    return v;
}
__device__ __forceinline__ void unpack2(u64 v, float& lo, float& hi) {
    asm("mov.b64 {%0, %1}, %2;" : "=f"(lo), "=f"(hi) : "l"(v));
}
#define BARS(id, cnt) asm volatile("bar.sync %0, %1;" :: "r"(id), "r"(cnt) : "memory")

__device__ __forceinline__ void split8(float4 v0, float4 v1, uint4& H0, uint4& H1) {
    __half2 p0 = __floats2half2_rn(v0.x, v0.y);
    __half2 p1 = __floats2half2_rn(v0.z, v0.w);
    __half2 p2 = __floats2half2_rn(v1.x, v1.y);
    __half2 p3 = __floats2half2_rn(v1.z, v1.w);
    float2 q0 = __half22float2(p0);
    float2 q1 = __half22float2(p1);
    float2 q2 = __half22float2(p2);
    float2 q3 = __half22float2(p3);
    __half2 r0 = __floats2half2_rn(v0.x - q0.x, v0.y - q0.y);
    __half2 r1 = __floats2half2_rn(v0.z - q1.x, v0.w - q1.y);
    __half2 r2 = __floats2half2_rn(v1.x - q2.x, v1.y - q2.y);
    __half2 r3 = __floats2half2_rn(v1.z - q3.x, v1.w - q3.y);
    H0 = make_uint4(*(uint32_t*)&p0, *(uint32_t*)&p1, *(uint32_t*)&p2, *(uint32_t*)&p3);
    H1 = make_uint4(*(uint32_t*)&r0, *(uint32_t*)&r1, *(uint32_t*)&r2, *(uint32_t*)&r3);
}

__global__ void zero_kernel() {
    int i = blockIdx.x * 256 + threadIdx.x;
    if (i < ROWS_TOTAL) g_sumsq[i] = 0.0f;
}

// ---------------- hybrid tensor(fp16x2-split) + FFMA2 GEMM, fused row sumsq ----------------
__global__ __launch_bounds__(512, 1)
void gemm_hybrid_kernel(const float* __restrict__ A,
                        const float* __restrict__ W,
                        const float* __restrict__ bias,
                        int row_off)
{
    extern __shared__ __align__(16) char smem[];
    float* smf = (float*)smem;
    const int tid = threadIdx.x;
    const int m0  = blockIdx.y * BM;
    const int n0  = blockIdx.x * BN;

    if (tid < 128) smf[BIAS_B / 4 + tid] = bias[n0 + tid];

    if (tid < 256) {
        // ===================== TENSOR GROUP (warps 0-7), k in [0, K_T) =====================
        const int wid = tid >> 5;
        const int lid = tid & 31;
        const int wm  = wid >> 2;
        const int wn  = wid & 3;
        const int r   = lid >> 2;
        const int cq  = lid & 3;

        const int ar = tid >> 1;
        const int ac = (tid & 1) << 3;
        const float* Aptr = A + (size_t)(m0 + ar) * K_DIM + ac;
        const float* Wptr = W + (size_t)(n0 + ar) * K_DIM + ac;
        const uint32_t s_off = (uint32_t)ar * (SH * 2) + (uint32_t)ac * 2;

        float acc[4][4][4];
#pragma unroll
        for (int i = 0; i < 4; i++)
#pragma unroll
            for (int j = 0; j < 4; j++)
#pragma unroll
                for (int q = 0; q < 4; q++) acc[i][j][q] = 0.f;

        float4 av0, av1, bv0, bv1;

#define LOADCHUNK(kc) do { \
        const float* ap_ = Aptr + (size_t)(kc) * BK; \
        av0 = *(const float4*)ap_;  av1 = *(const float4*)(ap_ + 4); \
        const float* wp_ = Wptr + (size_t)(kc) * BK; \
        bv0 = *(const float4*)wp_;  bv1 = *(const float4*)(wp_ + 4); \
    } while (0)

#define STORESTAGE(s) do { \
        char* st_ = smem + (s) * STAGE_B; \
        uint4 H0_, H1_; \
        split8(av0, av1, H0_, H1_); \
        *(uint4*)(st_ + AH0_B + s_off) = H0_; \
        *(uint4*)(st_ + AH1_B + s_off) = H1_; \
        split8(bv0, bv1, H0_, H1_); \
        *(uint4*)(st_ + BH0_B + s_off) = H0_; \
        *(uint4*)(st_ + BH1_B + s_off) = H1_; \
    } while (0)

        LOADCHUNK(0);
        STORESTAGE(0);
        LOADCHUNK(1);
        BARS(1, 256);

        for (int kc = 0; kc < NCHUNK_T; kc++) {
            const char* st = smem + (kc & 1) * STAGE_B;

            uint32_t b0h[4], b1h[4], b0l[4], b1l[4];
#pragma unroll
            for (int nf = 0; nf < 4; nf++) {
                const int off = ((wn * 32 + nf * 8 + r) * SH + 2 * cq) * 2;
                b0h[nf] = *(const uint32_t*)(st + BH0_B + off);
                b1h[nf] = *(const uint32_t*)(st + BH0_B + off + 16);
                b0l[nf] = *(const uint32_t*)(st + BH1_B + off);
                b1l[nf] = *(const uint32_t*)(st + BH1_B + off + 16);
            }

#pragma unroll
            for (int mf = 0; mf < 4; mf++) {
                const int off0 = ((wm * 64 + mf * 16 + r) * SH + 2 * cq) * 2;
                const int off1 = off0 + 8 * SH * 2;
                uint32_t ah0 = *(const uint32_t*)(st + AH0_B + off0);
                uint32_t ah1 = *(const uint32_t*)(st + AH0_B + off1);
                uint32_t ah2 = *(const uint32_t*)(st + AH0_B + off0 + 16);
                uint32_t ah3 = *(const uint32_t*)(st + AH0_B + off1 + 16);
                uint32_t al0 = *(const uint32_t*)(st + AH1_B + off0);
                uint32_t al1 = *(const uint32_t*)(st + AH1_B + off1);
                uint32_t al2 = *(const uint32_t*)(st + AH1_B + off0 + 16);
                uint32_t al3 = *(const uint32_t*)(st + AH1_B + off1 + 16);
#pragma unroll
                for (int nf = 0; nf < 4; nf++) {
                    mma16(acc[mf][nf], ah0, ah1, ah2, ah3, b0h[nf], b1h[nf]);
                    mma16(acc[mf][nf], ah0, ah1, ah2, ah3, b0l[nf], b1l[nf]);
                    mma16(acc[mf][nf], al0, al1, al2, al3, b0h[nf], b1h[nf]);
                }
            }

            if (kc + 1 < NCHUNK_T) {
                STORESTAGE((kc + 1) & 1);
                if (kc + 2 < NCHUNK_T) LOADCHUNK(kc + 2);
            }
            BARS(1, 256);
        }

        // join with FFMA group, then fold in fp32 partial + bias + square
        BARS(3, 512);

        const float* cs = smf + CS_B / 4;
        const float* sbias = smf + BIAS_B / 4;
#pragma unroll
        for (int mf = 0; mf < 4; mf++) {
            const int r0 = wm * 64 + mf * 16 + r;
            float rs0 = 0.f, rs1 = 0.f;
#pragma unroll
            for (int nf = 0; nf < 4; nf++) {
                const int nc = wn * 32 + nf * 8 + 2 * cq;
                const float* c0 = cs + r0 * CS_STRIDE_F + nc;
                const float* c1 = cs + (r0 + 8) * CS_STRIDE_F + nc;
                float b0 = sbias[nc], b1 = sbias[nc + 1];
                float v;
                v = acc[mf][nf][0] + c0[0] + b0; rs0 += v * v;
                v = acc[mf][nf][1] + c0[1] + b1; rs0 += v * v;
                v = acc[mf][nf][2] + c1[0] + b0; rs1 += v * v;
                v = acc[mf][nf][3] + c1[1] + b1; rs1 += v * v;
            }
            rs0 += __shfl_xor_sync(0xffffffffu, rs0, 1);
            rs0 += __shfl_xor_sync(0xffffffffu, rs0, 2);
            rs1 += __shfl_xor_sync(0xffffffffu, rs1, 1);
            rs1 += __shfl_xor_sync(0xffffffffu, rs1, 2);
            if (cq == 0) {
                const int mrow = row_off + m0 + r0;
                atomicAdd(&g_sumsq[mrow],     rs0);
                atomicAdd(&g_sumsq[mrow + 8], rs1);
            }
        }
    } else {
        // ===================== FFMA GROUP (warps 8-15), k in [KF_BASE, 2048) =====================
        const int t2   = tid - 256;            // 0..255
        const int nrow = t2 >> 1;              // 0..127 (load row)
        const int koff = (t2 & 1) << 3;        // 0 or 8
        const int rr   = t2 & 127;             // compute row
        const int colbase = (t2 >> 7) * 64;    // 0 or 64

        const float* Ag = A + (size_t)(m0 + nrow) * K_DIM + KF_BASE + koff;
        const float* Wg = W + (size_t)(n0 + nrow) * K_DIM + KF_BASE + koff;

        u64 acc2[32];
#pragma unroll
        for (int i = 0; i < 32; i++) acc2[i] = 0ull;

        float4 aw0, aw1, bw0, bw1;

#define LDGF(kc) do { \
        const float* ag_ = Ag + (size_t)(kc) * BK; \
        aw0 = *(const float4*)ag_;  aw1 = *(const float4*)(ag_ + 4); \
        const float* wg_ = Wg + (size_t)(kc) * BK; \
        bw0 = *(const float4*)wg_;  bw1 = *(const float4*)(wg_ + 4); \
    } while (0)

#define STSF(s) do { \
        float* as_ = smf + AS_B / 4 + (s) * AS_STAGE_F + nrow * AS_STRIDE_F + koff; \
        *(float4*)as_ = aw0; *(float4*)(as_ + 4) = aw1; \
        float* bs_ = smf + BS_B / 4 + (s) * BS_STAGE_F + nrow; \
        bs_[(koff + 0) * BS_STRIDE_F] = bw0.x; bs_[(koff + 1) * BS_STRIDE_F] = bw0.y; \
        bs_[(koff + 2) * BS_STRIDE_F] = bw0.z; bs_[(koff + 3) * BS_STRIDE_F] = bw0.w; \
        bs_[(koff + 4) * BS_STRIDE_F] = bw1.x; bs_[(koff + 5) * BS_STRIDE_F] = bw1.y; \
        bs_[(koff + 6) * BS_STRIDE_F] = bw1.z; bs_[(koff + 7) * BS_STRIDE_F] = bw1.w; \
    } while (0)

        LDGF(0);
        STSF(0);
        LDGF(1);
        BARS(2, 256);

        for (int kc2 = 0; kc2 < NF; kc2++) {
            const int s = kc2 & 1;
            const float* asb = smf + AS_B / 4 + s * AS_STAGE_F + rr * AS_STRIDE_F;
            float4 a04 = *(const float4*)asb;
            float4 a14 = *(const float4*)(asb + 4);
            float4 a24 = *(const float4*)(asb + 8);
            float4 a34 = *(const float4*)(asb + 12);
            float a16[16] = {a04.x, a04.y, a04.z, a04.w, a14.x, a14.y, a14.z, a14.w,
                             a24.x, a24.y, a24.z, a24.w, a34.x, a34.y, a34.z, a34.w};
            const float* bsb = smf + BS_B / 4 + s * BS_STAGE_F + colbase;

#pragma unroll
            for (int k = 0; k < 16; k++) {
                const float av = a16[k];
                const u64 a2 = pack2(av, av);
                const ulonglong2* bq = (const ulonglong2*)(bsb + k * BS_STRIDE_F);
#pragma unroll
                for (int blk = 0; blk < 4; blk++) {
                    ulonglong2 p0 = bq[blk * 4 + 0];
                    ulonglong2 p1 = bq[blk * 4 + 1];
                    ulonglong2 p2 = bq[blk * 4 + 2];
                    ulonglong2 p3 = bq[blk * 4 + 3];
                    acc2[blk * 8 + 0] = ffma2(a2, p0.x, acc2[blk * 8 + 0]);
                    acc2[blk * 8 + 1] = ffma2(a2, p0.y, acc2[blk * 8 + 1]);
                    acc2[blk * 8 + 2] = ffma2(a2, p1.x, acc2[blk * 8 + 2]);
                    acc2[blk * 8 + 3] = ffma2(a2, p1.y, acc2[blk * 8 + 3]);
                    acc2[blk * 8 + 4] = ffma2(a2, p2.x, acc2[blk * 8 + 4]);
                    acc2[blk * 8 + 5] = ffma2(a2, p2.y, acc2[blk * 8 + 5]);
                    acc2[blk * 8 + 6] = ffma2(a2, p3.x, acc2[blk * 8 + 6]);
                    acc2[blk * 8 + 7] = ffma2(a2, p3.y, acc2[blk * 8 + 7]);
                }
            }

            if (kc2 + 1 < NF) {
                STSF((kc2 + 1) & 1);
                if (kc2 + 2 < NF) LDGF(kc2 + 2);
            }
            BARS(2, 256);
        }

        // write fp32 partial C tile
        float* cs = smf + CS_B / 4 + rr * CS_STRIDE_F + colbase;
#pragma unroll
        for (int blk = 0; blk < 4; blk++)
#pragma unroll
            for (int q = 0; q < 4; q++) {
                float lo, hi;
                unpack2(acc2[blk * 8 + q * 2 + 0], lo, hi);
                cs[blk * 16 + q * 4 + 0] = lo;
                cs[blk * 16 + q * 4 + 1] = hi;
                unpack2(acc2[blk * 8 + q * 2 + 1], lo, hi);
                cs[blk * 16 + q * 4 + 2] = lo;
                cs[blk * 16 + q * 4 + 3] = hi;
            }

        BARS(3, 512);
        // done; tensor group performs the epilogue
    }
}

// ---------------- finalize ----------------
__global__ void finalize_kernel(const float* __restrict__ phi_scale,
                                const float* __restrict__ phi_bias,
                                float* __restrict__ out)
{
    const int b = blockIdx.x;
    const int tid = threadIdx.x;

    float lw = 0.f, lp = 0.f;
    for (int i = tid; i < 2048; i += 256)
        lw += sqrtf(g_sumsq[b * 2048 + i]);
#pragma unroll
    for (int h = 0; h < 4; h++) {
        int base = ROWS_WHOLE + h * ROWS_WHOLE + b * 2048;
        for (int i = tid; i < 2048; i += 256)
            lp += sqrtf(g_sumsq[base + i]);
    }

    __shared__ float sw[256];
    __shared__ float sp[256];
    sw[tid] = lw; sp[tid] = lp;
    __syncthreads();
    for (int s = 128; s > 0; s >>= 1) {
        if (tid < s) { sw[tid] += sw[tid + s]; sp[tid] += sp[tid + s]; }
        __syncthreads();
    }
    if (tid == 0) {
        float w = sw[0] / 2048.0f;
        float p = sp[0] / 8192.0f;
        float raw = (w - p) / (w + 1e-8f);
        float phi = phi_scale[0] * raw + phi_bias[0];
        out[b] = fminf(fmaxf(phi, 0.0f), 1.0f);
    }
}

extern "C" void kernel_launch(void* const* d_in, const int* in_sizes, int n_in,
                              void* d_out, int out_size)
{
    const float* cur  = (const float*)d_in[0];   // [4,2048,2048]
    const float* hist = (const float*)d_in[1];   // [4,4,2048,2048]
    const float* Ww   = (const float*)d_in[2];   // [1024,2048]
    const float* bw   = (const float*)d_in[3];   // [1024]
    const float* Wp   = (const float*)d_in[4];   // [1024,2048]
    const float* bp   = (const float*)d_in[5];   // [1024]
    const float* ps   = (const float*)d_in[6];
    const float* pb   = (const float*)d_in[7];
    float* out = (float*)d_out;                  // [4]

    cudaFuncSetAttribute(gemm_hybrid_kernel,
                         cudaFuncAttributeMaxDynamicSharedMemorySize, SMEM_BYTES);

    zero_kernel<<<(ROWS_TOTAL + 255) / 256, 256>>>();

    gemm_hybrid_kernel<<<dim3(N_DIM / BN, ROWS_WHOLE / BM), 512, SMEM_BYTES>>>(cur, Ww, bw, 0);
    gemm_hybrid_kernel<<<dim3(N_DIM / BN, ROWS_PARTS / BM), 512, SMEM_BYTES>>>(hist, Wp, bp, ROWS_WHOLE);

    finalize_kernel<<<4, 256>>>(ps, pb, out);
}

// round 8
// speedup vs baseline: 1.3943x; 1.3943x over previous
#include <cuda_runtime.h>
#include <cuda_fp16.h>
#include <cstdint>

// ---------------- problem constants ----------------
#define K_DIM       2048
#define N_DIM       1024
#define ROWS_WHOLE  8192
#define ROWS_PARTS  32768
#define ROWS_TOTAL  40960

// ---------------- tile / split config ----------------
#define BM 128
#define BN 128
#define BK 16
#define NT        93              // tensor chunks, k in [0, 1488)
#define NF        35              // FFMA chunks,  k in [1488, 2048)
#define KF_BASE   (NT * BK)       // 1488

// tensor-side SMEM stage (fp16 splits), stride 24 halves
#define SH 24
#define TERM_H   (BM * SH)
#define AH0_B    0
#define AH1_B    (TERM_H * 2)
#define BH0_B    (2 * TERM_H * 2)
#define BH1_B    (3 * TERM_H * 2)
#define STAGE_B  (4 * TERM_H * 2)      // 24576 bytes

// FFMA-side SMEM (float indices)
#define AS_F        12288              // 2 stages x 16 x 132 (k-major, transposed)
#define AS_STAGE_F  2112
#define BS_F        16512
#define BS_STAGE_F  2112
#define CS_F        20736              // 128 x 132 partial C
#define CS_STRIDE_F 132
#define BIAS_F      37632
#define SMEM_BYTES  151040

__device__ float g_sumsq[ROWS_TOTAL];

// ---------------- helpers ----------------
__device__ __forceinline__ void mma16(float* c,
                                      uint32_t a0, uint32_t a1, uint32_t a2, uint32_t a3,
                                      uint32_t b0, uint32_t b1) {
    asm volatile(
        "mma.sync.aligned.m16n8k16.row.col.f32.f16.f16.f32 "
        "{%0,%1,%2,%3}, {%4,%5,%6,%7}, {%8,%9}, {%0,%1,%2,%3};"
        : "+f"(c[0]), "+f"(c[1]), "+f"(c[2]), "+f"(c[3])
        : "r"(a0), "r"(a1), "r"(a2), "r"(a3), "r"(b0), "r"(b1));
}
#define BARS(id, cnt) asm volatile("bar.sync %0, %1;" :: "r"(id), "r"(cnt) : "memory")

__device__ __forceinline__ void split8(float4 v0, float4 v1, uint4& H0, uint4& H1) {
    __half2 p0 = __floats2half2_rn(v0.x, v0.y);
    __half2 p1 = __floats2half2_rn(v0.z, v0.w);
    __half2 p2 = __floats2half2_rn(v1.x, v1.y);
    __half2 p3 = __floats2half2_rn(v1.z, v1.w);
    float2 q0 = __half22float2(p0);
    float2 q1 = __half22float2(p1);
    float2 q2 = __half22float2(p2);
    float2 q3 = __half22float2(p3);
    __half2 r0 = __floats2half2_rn(v0.x - q0.x, v0.y - q0.y);
    __half2 r1 = __floats2half2_rn(v0.z - q1.x, v0.w - q1.y);
    __half2 r2 = __floats2half2_rn(v1.x - q2.x, v1.y - q2.y);
    __half2 r3 = __floats2half2_rn(v1.z - q3.x, v1.w - q3.y);
    H0 = make_uint4(*(uint32_t*)&p0, *(uint32_t*)&p1, *(uint32_t*)&p2, *(uint32_t*)&p3);
    H1 = make_uint4(*(uint32_t*)&r0, *(uint32_t*)&r1, *(uint32_t*)&r2, *(uint32_t*)&r3);
}

__global__ void zero_kernel() {
    int i = blockIdx.x * 256 + threadIdx.x;
    if (i < ROWS_TOTAL) g_sumsq[i] = 0.0f;
}

// ---------------- hybrid: tensor fp16x2-split (k<1488) + fp32 FFMA (k>=1488) ----------------
__global__ __launch_bounds__(512, 1)
void gemm_hybrid_kernel(const float* __restrict__ A,
                        const float* __restrict__ W,
                        const float* __restrict__ bias,
                        int row_off)
{
    extern __shared__ __align__(16) char smem[];
    float* smf = (float*)smem;
    const int tid = threadIdx.x;
    const int m0  = blockIdx.y * BM;
    const int n0  = blockIdx.x * BN;

    if (tid < 128) smf[BIAS_F + tid] = bias[n0 + tid];

    if (tid < 256) {
        // ============ TENSOR GROUP (warps 0-7), k in [0, KF_BASE) ============
        const int wid = tid >> 5;
        const int lid = tid & 31;
        const int wm  = wid >> 2;
        const int wn  = wid & 3;
        const int r   = lid >> 2;
        const int cq  = lid & 3;

        const int ar = tid >> 1;
        const int ac = (tid & 1) << 3;
        const float* Aptr = A + (size_t)(m0 + ar) * K_DIM + ac;
        const float* Wptr = W + (size_t)(n0 + ar) * K_DIM + ac;
        const uint32_t s_off = (uint32_t)ar * (SH * 2) + (uint32_t)ac * 2;

        float acc[4][4][4];
#pragma unroll
        for (int i = 0; i < 4; i++)
#pragma unroll
            for (int j = 0; j < 4; j++)
#pragma unroll
                for (int q = 0; q < 4; q++) acc[i][j][q] = 0.f;

        float4 av0, av1, bv0, bv1;

#define LOADCHUNK(kc) do { \
        const float* ap_ = Aptr + (size_t)(kc) * BK; \
        av0 = *(const float4*)ap_;  av1 = *(const float4*)(ap_ + 4); \
        const float* wp_ = Wptr + (size_t)(kc) * BK; \
        bv0 = *(const float4*)wp_;  bv1 = *(const float4*)(wp_ + 4); \
    } while (0)

#define STORESTAGE(s) do { \
        char* st_ = smem + (s) * STAGE_B; \
        uint4 H0_, H1_; \
        split8(av0, av1, H0_, H1_); \
        *(uint4*)(st_ + AH0_B + s_off) = H0_; \
        *(uint4*)(st_ + AH1_B + s_off) = H1_; \
        split8(bv0, bv1, H0_, H1_); \
        *(uint4*)(st_ + BH0_B + s_off) = H0_; \
        *(uint4*)(st_ + BH1_B + s_off) = H1_; \
    } while (0)

        LOADCHUNK(0);
        STORESTAGE(0);
        LOADCHUNK(1);
        BARS(1, 256);

        for (int kc = 0; kc < NT; kc++) {
            const char* st = smem + (kc & 1) * STAGE_B;

            uint32_t b0h[4], b1h[4], b0l[4], b1l[4];
#pragma unroll
            for (int nf = 0; nf < 4; nf++) {
                const int off = ((wn * 32 + nf * 8 + r) * SH + 2 * cq) * 2;
                b0h[nf] = *(const uint32_t*)(st + BH0_B + off);
                b1h[nf] = *(const uint32_t*)(st + BH0_B + off + 16);
                b0l[nf] = *(const uint32_t*)(st + BH1_B + off);
                b1l[nf] = *(const uint32_t*)(st + BH1_B + off + 16);
            }

#pragma unroll
            for (int mf = 0; mf < 4; mf++) {
                const int off0 = ((wm * 64 + mf * 16 + r) * SH + 2 * cq) * 2;
                const int off1 = off0 + 8 * SH * 2;
                uint32_t ah0 = *(const uint32_t*)(st + AH0_B + off0);
                uint32_t ah1 = *(const uint32_t*)(st + AH0_B + off1);
                uint32_t ah2 = *(const uint32_t*)(st + AH0_B + off0 + 16);
                uint32_t ah3 = *(const uint32_t*)(st + AH0_B + off1 + 16);
                uint32_t al0 = *(const uint32_t*)(st + AH1_B + off0);
                uint32_t al1 = *(const uint32_t*)(st + AH1_B + off1);
                uint32_t al2 = *(const uint32_t*)(st + AH1_B + off0 + 16);
                uint32_t al3 = *(const uint32_t*)(st + AH1_B + off1 + 16);
#pragma unroll
                for (int nf = 0; nf < 4; nf++) {
                    mma16(acc[mf][nf], ah0, ah1, ah2, ah3, b0h[nf], b1h[nf]);
                    mma16(acc[mf][nf], ah0, ah1, ah2, ah3, b0l[nf], b1l[nf]);
                    mma16(acc[mf][nf], al0, al1, al2, al3, b0h[nf], b1h[nf]);
                }
            }

            if (kc + 1 < NT) {
                STORESTAGE((kc + 1) & 1);
                if (kc + 2 < NT) LOADCHUNK(kc + 2);
            }
            BARS(1, 256);
        }

        // join with FFMA group, then fold fp32 partial + bias + square
        BARS(3, 512);

        const float* cs = smf + CS_F;
        const float* sbias = smf + BIAS_F;
#pragma unroll
        for (int mf = 0; mf < 4; mf++) {
            const int r0 = wm * 64 + mf * 16 + r;
            float rs0 = 0.f, rs1 = 0.f;
#pragma unroll
            for (int nf = 0; nf < 4; nf++) {
                const int nc = wn * 32 + nf * 8 + 2 * cq;
                const float* c0 = cs + r0 * CS_STRIDE_F + nc;
                const float* c1 = cs + (r0 + 8) * CS_STRIDE_F + nc;
                float b0 = sbias[nc], b1 = sbias[nc + 1];
                float v;
                v = acc[mf][nf][0] + c0[0] + b0; rs0 += v * v;
                v = acc[mf][nf][1] + c0[1] + b1; rs0 += v * v;
                v = acc[mf][nf][2] + c1[0] + b0; rs1 += v * v;
                v = acc[mf][nf][3] + c1[1] + b1; rs1 += v * v;
            }
            rs0 += __shfl_xor_sync(0xffffffffu, rs0, 1);
            rs0 += __shfl_xor_sync(0xffffffffu, rs0, 2);
            rs1 += __shfl_xor_sync(0xffffffffu, rs1, 1);
            rs1 += __shfl_xor_sync(0xffffffffu, rs1, 2);
            if (cq == 0) {
                const int mrow = row_off + m0 + r0;
                atomicAdd(&g_sumsq[mrow],     rs0);
                atomicAdd(&g_sumsq[mrow + 8], rs1);
            }
        }
    } else {
        // ============ FFMA GROUP (warps 8-15), k in [KF_BASE, 2048) ============
        const int t2   = tid - 256;            // 0..255
        const int tcol = t2 & 15;
        const int trow = t2 >> 4;
        const int ar   = t2 >> 1;              // loader row 0..127
        const int koff = (t2 & 1) << 3;        // 0 or 8

        const float* Ag = A + (size_t)(m0 + ar) * K_DIM + KF_BASE + koff;
        const float* Wg = W + (size_t)(n0 + ar) * K_DIM + KF_BASE + koff;

        float acc2[8][8];
#pragma unroll
        for (int i = 0; i < 8; i++)
#pragma unroll
            for (int j = 0; j < 8; j++) acc2[i][j] = 0.f;

        float4 aw0, aw1, bw0, bw1;

#define LDGF(kc) do { \
        const float* ag_ = Ag + (size_t)(kc) * BK; \
        aw0 = *(const float4*)ag_;  aw1 = *(const float4*)(ag_ + 4); \
        const float* wg_ = Wg + (size_t)(kc) * BK; \
        bw0 = *(const float4*)wg_;  bw1 = *(const float4*)(wg_ + 4); \
    } while (0)

#define STSF(s) do { \
        float* as_ = smf + AS_F + (s) * AS_STAGE_F + ar; \
        as_[(koff + 0) * 132] = aw0.x; as_[(koff + 1) * 132] = aw0.y; \
        as_[(koff + 2) * 132] = aw0.z; as_[(koff + 3) * 132] = aw0.w; \
        as_[(koff + 4) * 132] = aw1.x; as_[(koff + 5) * 132] = aw1.y; \
        as_[(koff + 6) * 132] = aw1.z; as_[(koff + 7) * 132] = aw1.w; \
        float* bs_ = smf + BS_F + (s) * BS_STAGE_F + ar; \
        bs_[(koff + 0) * 132] = bw0.x; bs_[(koff + 1) * 132] = bw0.y; \
        bs_[(koff + 2) * 132] = bw0.z; bs_[(koff + 3) * 132] = bw0.w; \
        bs_[(koff + 4) * 132] = bw1.x; bs_[(koff + 5) * 132] = bw1.y; \
        bs_[(koff + 6) * 132] = bw1.z; bs_[(koff + 7) * 132] = bw1.w; \
    } while (0)

        LDGF(0);
        STSF(0);
        LDGF(1);
        BARS(2, 256);

        for (int kc2 = 0; kc2 < NF; kc2++) {
            const int s = kc2 & 1;
            const float* As_ = smf + AS_F + s * AS_STAGE_F;
            const float* Bs_ = smf + BS_F + s * BS_STAGE_F;

#pragma unroll
            for (int k = 0; k < 16; k++) {
                float4 a0 = *(const float4*)(As_ + k * 132 + trow * 4);
                float4 a1 = *(const float4*)(As_ + k * 132 + 64 + trow * 4);
                float4 b0 = *(const float4*)(Bs_ + k * 132 + tcol * 4);
                float4 b1 = *(const float4*)(Bs_ + k * 132 + 64 + tcol * 4);
                float af[8] = {a0.x, a0.y, a0.z, a0.w, a1.x, a1.y, a1.z, a1.w};
                float bf[8] = {b0.x, b0.y, b0.z, b0.w, b1.x, b1.y, b1.z, b1.w};
#pragma unroll
                for (int i = 0; i < 8; i++)
#pragma unroll
                    for (int j = 0; j < 8; j++)
                        acc2[i][j] += af[i] * bf[j];
            }

            if (kc2 + 1 < NF) {
                STSF((kc2 + 1) & 1);
                if (kc2 + 2 < NF) LDGF(kc2 + 2);
            }
            BARS(2, 256);
        }

        // write fp32 partial C tile (vectorized)
        float* cs = smf + CS_F;
#pragma unroll
        for (int i = 0; i < 8; i++) {
            const int rm = trow * 4 + (i & 3) + (i >> 2) * 64;
            float* c_ = cs + rm * CS_STRIDE_F + tcol * 4;
            *(float4*)c_        = make_float4(acc2[i][0], acc2[i][1], acc2[i][2], acc2[i][3]);
            *(float4*)(c_ + 64) = make_float4(acc2[i][4], acc2[i][5], acc2[i][6], acc2[i][7]);
        }

        BARS(3, 512);
        // tensor group performs the epilogue
    }
}

// ---------------- finalize ----------------
__global__ void finalize_kernel(const float* __restrict__ phi_scale,
                                const float* __restrict__ phi_bias,
                                float* __restrict__ out)
{
    const int b = blockIdx.x;
    const int tid = threadIdx.x;

    float lw = 0.f, lp = 0.f;
    for (int i = tid; i < 2048; i += 256)
        lw += sqrtf(g_sumsq[b * 2048 + i]);
#pragma unroll
    for (int h = 0; h < 4; h++) {
        int base = ROWS_WHOLE + h * ROWS_WHOLE + b * 2048;
        for (int i = tid; i < 2048; i += 256)
            lp += sqrtf(g_sumsq[base + i]);
    }

    __shared__ float sw[256];
    __shared__ float sp[256];
    sw[tid] = lw; sp[tid] = lp;
    __syncthreads();
    for (int s = 128; s > 0; s >>= 1) {
        if (tid < s) { sw[tid] += sw[tid + s]; sp[tid] += sp[tid + s]; }
        __syncthreads();
    }
    if (tid == 0) {
        float w = sw[0] / 2048.0f;
        float p = sp[0] / 8192.0f;
        float raw = (w - p) / (w + 1e-8f);
        float phi = phi_scale[0] * raw + phi_bias[0];
        out[b] = fminf(fmaxf(phi, 0.0f), 1.0f);
    }
}

extern "C" void kernel_launch(void* const* d_in, const int* in_sizes, int n_in,
                              void* d_out, int out_size)
{
    const float* cur  = (const float*)d_in[0];   // [4,2048,2048]
    const float* hist = (const float*)d_in[1];   // [4,4,2048,2048]
    const float* Ww   = (const float*)d_in[2];   // [1024,2048]
    const float* bw   = (const float*)d_in[3];   // [1024]
    const float* Wp   = (const float*)d_in[4];   // [1024,2048]
    const float* bp   = (const float*)d_in[5];   // [1024]
    const float* ps   = (const float*)d_in[6];
    const float* pb   = (const float*)d_in[7];
    float* out = (float*)d_out;                  // [4]

    cudaFuncSetAttribute(gemm_hybrid_kernel,
                         cudaFuncAttributeMaxDynamicSharedMemorySize, SMEM_BYTES);

    zero_kernel<<<(ROWS_TOTAL + 255) / 256, 256>>>();

    gemm_hybrid_kernel<<<dim3(N_DIM / BN, ROWS_WHOLE / BM), 512, SMEM_BYTES>>>(cur, Ww, bw, 0);
    gemm_hybrid_kernel<<<dim3(N_DIM / BN, ROWS_PARTS / BM), 512, SMEM_BYTES>>>(hist, Wp, bp, ROWS_WHOLE);

    finalize_kernel<<<4, 256>>>(ps, pb, out);
}

// round 10
// speedup vs baseline: 1.7082x; 1.2251x over previous
#include <cuda_runtime.h>
#include <cuda_fp16.h>
#include <cstdint>

// ---------------- problem constants ----------------
#define K_DIM       2048
#define N_DIM       1024
#define ROWS_WHOLE  8192
#define ROWS_PARTS  32768
#define ROWS_TOTAL  40960

// ---------------- tile config ----------------
#define BM 128
#define BN 128
#define BK 16
#define NCHUNK (K_DIM / BK)        // 128
#define SH 24                      // halves per smem row (48B stride, conflict-free)

#define LO_SCALE    4096.0f        // residuals pre-scaled by 2^12
#define LO_INV      (1.0f / 4096.0f)

#define TERM_H   (BM * SH)
#define AH0_B    0
#define AH1_B    (TERM_H * 2)
#define BH0_B    (2 * TERM_H * 2)
#define BH1_B    (3 * TERM_H * 2)
#define STAGE_B  (4 * TERM_H * 2)      // 24576 bytes per stage
#define BIAS_B   (2 * STAGE_B)
#define SMEM_BYTES (BIAS_B + BN * 4)   // 49664

__device__ float g_sumsq[ROWS_TOTAL];

// ---------------- helpers ----------------
// fp32-accumulator fp16 MMA (main term)
__device__ __forceinline__ void mma16(float* c,
                                      uint32_t a0, uint32_t a1, uint32_t a2, uint32_t a3,
                                      uint32_t b0, uint32_t b1) {
    asm volatile(
        "mma.sync.aligned.m16n8k16.row.col.f32.f16.f16.f32 "
        "{%0,%1,%2,%3}, {%4,%5,%6,%7}, {%8,%9}, {%0,%1,%2,%3};"
        : "+f"(c[0]), "+f"(c[1]), "+f"(c[2]), "+f"(c[3])
        : "r"(a0), "r"(a1), "r"(a2), "r"(a3), "r"(b0), "r"(b1));
}
// fp16-accumulator fp16 MMA (cross terms; C/D = 2 x b32 = 4 halves)
__device__ __forceinline__ void mma16h(uint32_t* c,
                                       uint32_t a0, uint32_t a1, uint32_t a2, uint32_t a3,
                                       uint32_t b0, uint32_t b1) {
    asm volatile(
        "mma.sync.aligned.m16n8k16.row.col.f16.f16.f16.f16 "
        "{%0,%1}, {%2,%3,%4,%5}, {%6,%7}, {%0,%1};"
        : "+r"(c[0]), "+r"(c[1])
        : "r"(a0), "r"(a1), "r"(a2), "r"(a3), "r"(b0), "r"(b1));
}

// split 8 consecutive-k floats: H0 = fp16(v), H1 = fp16((v - H0) * 4096)
__device__ __forceinline__ void split8(float4 v0, float4 v1, uint4& H0, uint4& H1) {
    __half2 p0 = __floats2half2_rn(v0.x, v0.y);
    __half2 p1 = __floats2half2_rn(v0.z, v0.w);
    __half2 p2 = __floats2half2_rn(v1.x, v1.y);
    __half2 p3 = __floats2half2_rn(v1.z, v1.w);
    float2 q0 = __half22float2(p0);
    float2 q1 = __half22float2(p1);
    float2 q2 = __half22float2(p2);
    float2 q3 = __half22float2(p3);
    __half2 r0 = __floats2half2_rn((v0.x - q0.x) * LO_SCALE, (v0.y - q0.y) * LO_SCALE);
    __half2 r1 = __floats2half2_rn((v0.z - q1.x) * LO_SCALE, (v0.w - q1.y) * LO_SCALE);
    __half2 r2 = __floats2half2_rn((v1.x - q2.x) * LO_SCALE, (v1.y - q2.y) * LO_SCALE);
    __half2 r3 = __floats2half2_rn((v1.z - q3.x) * LO_SCALE, (v1.w - q3.y) * LO_SCALE);
    H0 = make_uint4(*(uint32_t*)&p0, *(uint32_t*)&p1, *(uint32_t*)&p2, *(uint32_t*)&p3);
    H1 = make_uint4(*(uint32_t*)&r0, *(uint32_t*)&r1, *(uint32_t*)&r2, *(uint32_t*)&r3);
}

__global__ void zero_kernel() {
    int i = blockIdx.x * 256 + threadIdx.x;
    if (i < ROWS_TOTAL) g_sumsq[i] = 0.0f;
}

// ---------------- fp16x2-split GEMM, cross terms in fp16 accum ----------------
__global__ __launch_bounds__(256)
void gemm_fp16x2_kernel(const float* __restrict__ A,
                        const float* __restrict__ W,
                        const float* __restrict__ bias,
                        int row_off)
{
    extern __shared__ __align__(16) char smem[];
    const int tid = threadIdx.x;
    const int wid = tid >> 5;
    const int lid = tid & 31;
    const int wm  = wid >> 2;
    const int wn  = wid & 3;
    const int r   = lid >> 2;
    const int cq  = lid & 3;
    const int m0  = blockIdx.y * BM;
    const int n0  = blockIdx.x * BN;

    float* sbias = (float*)(smem + BIAS_B);
    if (tid < BN) sbias[tid] = bias[n0 + tid];

    const int ar = tid >> 1;
    const int ac = (tid & 1) << 3;
    const float* Aptr = A + (size_t)(m0 + ar) * K_DIM + ac;
    const float* Wptr = W + (size_t)(n0 + ar) * K_DIM + ac;
    const uint32_t s_off = (uint32_t)ar * (SH * 2) + (uint32_t)ac * 2;

    float acc[4][4][4];        // fp32 main accumulators
    uint32_t acch[4][4][2];    // fp16 cross accumulators (scaled by 2^12)
#pragma unroll
    for (int i = 0; i < 4; i++)
#pragma unroll
        for (int j = 0; j < 4; j++) {
#pragma unroll
            for (int q = 0; q < 4; q++) acc[i][j][q] = 0.f;
            acch[i][j][0] = 0u; acch[i][j][1] = 0u;
        }

    float4 av0, av1, bv0, bv1;

#define LOADCHUNK(kc) do { \
        const float* ap_ = Aptr + (size_t)(kc) * BK; \
        av0 = *(const float4*)ap_;  av1 = *(const float4*)(ap_ + 4); \
        const float* wp_ = Wptr + (size_t)(kc) * BK; \
        bv0 = *(const float4*)wp_;  bv1 = *(const float4*)(wp_ + 4); \
    } while (0)

#define STORESTAGE(s) do { \
        char* st_ = smem + (s) * STAGE_B; \
        uint4 H0_, H1_; \
        split8(av0, av1, H0_, H1_); \
        *(uint4*)(st_ + AH0_B + s_off) = H0_; \
        *(uint4*)(st_ + AH1_B + s_off) = H1_; \
        split8(bv0, bv1, H0_, H1_); \
        *(uint4*)(st_ + BH0_B + s_off) = H0_; \
        *(uint4*)(st_ + BH1_B + s_off) = H1_; \
    } while (0)

    LOADCHUNK(0);
    STORESTAGE(0);
    LOADCHUNK(1);
    __syncthreads();

    for (int kc = 0; kc < NCHUNK; kc++) {
        const char* st = smem + (kc & 1) * STAGE_B;

        uint32_t b0h[4], b1h[4], b0l[4], b1l[4];
#pragma unroll
        for (int nf = 0; nf < 4; nf++) {
            const int off = ((wn * 32 + nf * 8 + r) * SH + 2 * cq) * 2;
            b0h[nf] = *(const uint32_t*)(st + BH0_B + off);
            b1h[nf] = *(const uint32_t*)(st + BH0_B + off + 16);
            b0l[nf] = *(const uint32_t*)(st + BH1_B + off);
            b1l[nf] = *(const uint32_t*)(st + BH1_B + off + 16);
        }

#pragma unroll
        for (int mf = 0; mf < 4; mf++) {
            const int off0 = ((wm * 64 + mf * 16 + r) * SH + 2 * cq) * 2;
            const int off1 = off0 + 8 * SH * 2;
            uint32_t ah0 = *(const uint32_t*)(st + AH0_B + off0);
            uint32_t ah1 = *(const uint32_t*)(st + AH0_B + off1);
            uint32_t ah2 = *(const uint32_t*)(st + AH0_B + off0 + 16);
            uint32_t ah3 = *(const uint32_t*)(st + AH0_B + off1 + 16);
            uint32_t al0 = *(const uint32_t*)(st + AH1_B + off0);
            uint32_t al1 = *(const uint32_t*)(st + AH1_B + off1);
            uint32_t al2 = *(const uint32_t*)(st + AH1_B + off0 + 16);
            uint32_t al3 = *(const uint32_t*)(st + AH1_B + off1 + 16);
#pragma unroll
            for (int nf = 0; nf < 4; nf++) {
                mma16 (acc[mf][nf],  ah0, ah1, ah2, ah3, b0h[nf], b1h[nf]);  // h0*h0 (fp32 acc)
                mma16h(acch[mf][nf], ah0, ah1, ah2, ah3, b0l[nf], b1l[nf]);  // h0*lo' (fp16 acc)
                mma16h(acch[mf][nf], al0, al1, al2, al3, b0h[nf], b1h[nf]);  // lo'*h0 (fp16 acc)
            }
        }

        if (kc + 1 < NCHUNK) {
            STORESTAGE((kc + 1) & 1);
            if (kc + 2 < NCHUNK) LOADCHUNK(kc + 2);
        }
        __syncthreads();
    }

    // ---------------- epilogue: combine, bias, square, per-row reduce, atomic ----------------
#pragma unroll
    for (int mf = 0; mf < 4; mf++) {
        float rs0 = 0.f, rs1 = 0.f;
#pragma unroll
        for (int nf = 0; nf < 4; nf++) {
            const int nc = wn * 32 + nf * 8 + 2 * cq;
            float b0 = sbias[nc], b1 = sbias[nc + 1];
            __half2 x0 = *(__half2*)&acch[mf][nf][0];   // rows r,   cols 2cq / 2cq+1
            __half2 x1 = *(__half2*)&acch[mf][nf][1];   // rows r+8
            float2 c0 = __half22float2(x0);
            float2 c1 = __half22float2(x1);
            float v;
            v = acc[mf][nf][0] + c0.x * LO_INV + b0; rs0 += v * v;
            v = acc[mf][nf][1] + c0.y * LO_INV + b1; rs0 += v * v;
            v = acc[mf][nf][2] + c1.x * LO_INV + b0; rs1 += v * v;
            v = acc[mf][nf][3] + c1.y * LO_INV + b1; rs1 += v * v;
        }
        rs0 += __shfl_xor_sync(0xffffffffu, rs0, 1);
        rs0 += __shfl_xor_sync(0xffffffffu, rs0, 2);
        rs1 += __shfl_xor_sync(0xffffffffu, rs1, 1);
        rs1 += __shfl_xor_sync(0xffffffffu, rs1, 2);
        if (cq == 0) {
            const int mrow = row_off + m0 + wm * 64 + mf * 16 + r;
            atomicAdd(&g_sumsq[mrow],     rs0);
            atomicAdd(&g_sumsq[mrow + 8], rs1);
        }
    }
}

// ---------------- finalize ----------------
__global__ void finalize_kernel(const float* __restrict__ phi_scale,
                                const float* __restrict__ phi_bias,
                                float* __restrict__ out)
{
    const int b = blockIdx.x;
    const int tid = threadIdx.x;

    float lw = 0.f, lp = 0.f;
    for (int i = tid; i < 2048; i += 256)
        lw += sqrtf(g_sumsq[b * 2048 + i]);
#pragma unroll
    for (int h = 0; h < 4; h++) {
        int base = ROWS_WHOLE + h * ROWS_WHOLE + b * 2048;
        for (int i = tid; i < 2048; i += 256)
            lp += sqrtf(g_sumsq[base + i]);
    }

    __shared__ float sw[256];
    __shared__ float sp[256];
    sw[tid] = lw; sp[tid] = lp;
    __syncthreads();
    for (int s = 128; s > 0; s >>= 1) {
        if (tid < s) { sw[tid] += sw[tid + s]; sp[tid] += sp[tid + s]; }
        __syncthreads();
    }
    if (tid == 0) {
        float w = sw[0] / 2048.0f;
        float p = sp[0] / 8192.0f;
        float raw = (w - p) / (w + 1e-8f);
        float phi = phi_scale[0] * raw + phi_bias[0];
        out[b] = fminf(fmaxf(phi, 0.0f), 1.0f);
    }
}

extern "C" void kernel_launch(void* const* d_in, const int* in_sizes, int n_in,
                              void* d_out, int out_size)
{
    const float* cur  = (const float*)d_in[0];   // [4,2048,2048]
    const float* hist = (const float*)d_in[1];   // [4,4,2048,2048]
    const float* Ww   = (const float*)d_in[2];   // [1024,2048]
    const float* bw   = (const float*)d_in[3];   // [1024]
    const float* Wp   = (const float*)d_in[4];   // [1024,2048]
    const float* bp   = (const float*)d_in[5];   // [1024]
    const float* ps   = (const float*)d_in[6];
    const float* pb   = (const float*)d_in[7];
    float* out = (float*)d_out;                  // [4]

    cudaFuncSetAttribute(gemm_fp16x2_kernel,
                         cudaFuncAttributeMaxDynamicSharedMemorySize, SMEM_BYTES);

    zero_kernel<<<(ROWS_TOTAL + 255) / 256, 256>>>();

    gemm_fp16x2_kernel<<<dim3(N_DIM / BN, ROWS_WHOLE / BM), 256, SMEM_BYTES>>>(cur, Ww, bw, 0);
    gemm_fp16x2_kernel<<<dim3(N_DIM / BN, ROWS_PARTS / BM), 256, SMEM_BYTES>>>(hist, Wp, bp, ROWS_WHOLE);

    finalize_kernel<<<4, 256>>>(ps, pb, out);
}

// round 11
// speedup vs baseline: 1.9852x; 1.1622x over previous
#include <cuda_runtime.h>
#include <cuda_fp16.h>
#include <cstdint>

// ---------------- problem constants ----------------
#define K_DIM       2048
#define N_DIM       1024
#define ROWS_WHOLE  8192
#define ROWS_PARTS  32768
#define ROWS_TOTAL  40960
#define MB_WHOLE    64             // 8192/128 m-blocks for "whole"
#define MB_TOTAL    320            // + 32768/128 for "parts"

// ---------------- tile config (R6 architecture) ----------------
#define BM 128
#define BN 128
#define BK 16
#define NCHUNK (K_DIM / BK)        // 128
#define SH 24                      // halves per smem row (48B stride, conflict-free)

#define TERM_H   (BM * SH)
#define AH0_B    0
#define AH1_B    (TERM_H * 2)
#define BH0_B    (2 * TERM_H * 2)
#define BH1_B    (3 * TERM_H * 2)
#define STAGE_B  (4 * TERM_H * 2)      // 24576 bytes per stage
#define BIAS_B   (2 * STAGE_B)
#define SMEM_BYTES (BIAS_B + BN * 4)   // 49664

__device__ float g_sumsq[ROWS_TOTAL];

// ---------------- helpers ----------------
__device__ __forceinline__ void mma16(float* c,
                                      uint32_t a0, uint32_t a1, uint32_t a2, uint32_t a3,
                                      uint32_t b0, uint32_t b1) {
    asm volatile(
        "mma.sync.aligned.m16n8k16.row.col.f32.f16.f16.f32 "
        "{%0,%1,%2,%3}, {%4,%5,%6,%7}, {%8,%9}, {%0,%1,%2,%3};"
        : "+f"(c[0]), "+f"(c[1]), "+f"(c[2]), "+f"(c[3])
        : "r"(a0), "r"(a1), "r"(a2), "r"(a3), "r"(b0), "r"(b1));
}

// split 8 consecutive-k floats into packed fp16 h0 and residual h1
__device__ __forceinline__ void split8(float4 v0, float4 v1, uint4& H0, uint4& H1) {
    __half2 p0 = __floats2half2_rn(v0.x, v0.y);
    __half2 p1 = __floats2half2_rn(v0.z, v0.w);
    __half2 p2 = __floats2half2_rn(v1.x, v1.y);
    __half2 p3 = __floats2half2_rn(v1.z, v1.w);
    float2 q0 = __half22float2(p0);
    float2 q1 = __half22float2(p1);
    float2 q2 = __half22float2(p2);
    float2 q3 = __half22float2(p3);
    __half2 r0 = __floats2half2_rn(v0.x - q0.x, v0.y - q0.y);
    __half2 r1 = __floats2half2_rn(v0.z - q1.x, v0.w - q1.y);
    __half2 r2 = __floats2half2_rn(v1.x - q2.x, v1.y - q2.y);
    __half2 r3 = __floats2half2_rn(v1.z - q3.x, v1.w - q3.y);
    H0 = make_uint4(*(uint32_t*)&p0, *(uint32_t*)&p1, *(uint32_t*)&p2, *(uint32_t*)&p3);
    H1 = make_uint4(*(uint32_t*)&r0, *(uint32_t*)&r1, *(uint32_t*)&r2, *(uint32_t*)&r3);
}

__global__ void zero_kernel() {
    int i = blockIdx.x * 256 + threadIdx.x;
    if (i < ROWS_TOTAL) g_sumsq[i] = 0.0f;
}

// ---------------- merged fp16x2-split GEMM + row sum-of-squares ----------------
// blockIdx.y < MB_WHOLE  -> whole:  A=cur,  W=Ww, bias=bw, rows [0, 8192)
// blockIdx.y >= MB_WHOLE -> parts:  A=hist, W=Wp, bias=bp, rows [8192, 40960)
__global__ __launch_bounds__(256, 2)
void gemm_fp16x2_kernel(const float* __restrict__ Acur,
                        const float* __restrict__ Ahist,
                        const float* __restrict__ Ww,
                        const float* __restrict__ bw,
                        const float* __restrict__ Wp,
                        const float* __restrict__ bp)
{
    extern __shared__ __align__(16) char smem[];
    const int tid = threadIdx.x;
    const int wid = tid >> 5;
    const int lid = tid & 31;
    const int wm  = wid >> 2;
    const int wn  = wid & 3;
    const int r   = lid >> 2;
    const int cq  = lid & 3;
    const int by  = blockIdx.y;
    const int n0  = blockIdx.x * BN;

    const bool is_whole = (by < MB_WHOLE);
    const float* A    = is_whole ? Acur : Ahist;
    const float* W    = is_whole ? Ww   : Wp;
    const float* bias = is_whole ? bw   : bp;
    const int m0      = (is_whole ? by : (by - MB_WHOLE)) * BM;
    const int row_off = is_whole ? 0 : ROWS_WHOLE;

    float* sbias = (float*)(smem + BIAS_B);
    if (tid < BN) sbias[tid] = bias[n0 + tid];

    const int ar = tid >> 1;
    const int ac = (tid & 1) << 3;
    const float* Aptr = A + (size_t)(m0 + ar) * K_DIM + ac;
    const float* Wptr = W + (size_t)(n0 + ar) * K_DIM + ac;
    const uint32_t s_off = (uint32_t)ar * (SH * 2) + (uint32_t)ac * 2;

    float acc[4][4][4];
#pragma unroll
    for (int i = 0; i < 4; i++)
#pragma unroll
        for (int j = 0; j < 4; j++)
#pragma unroll
            for (int q = 0; q < 4; q++) acc[i][j][q] = 0.f;

    float4 av0, av1, bv0, bv1;

#define LOADCHUNK(kc) do { \
        const float* ap_ = Aptr + (size_t)(kc) * BK; \
        av0 = *(const float4*)ap_;  av1 = *(const float4*)(ap_ + 4); \
        const float* wp_ = Wptr + (size_t)(kc) * BK; \
        bv0 = *(const float4*)wp_;  bv1 = *(const float4*)(wp_ + 4); \
    } while (0)

#define STORESTAGE(s) do { \
        char* st_ = smem + (s) * STAGE_B; \
        uint4 H0_, H1_; \
        split8(av0, av1, H0_, H1_); \
        *(uint4*)(st_ + AH0_B + s_off) = H0_; \
        *(uint4*)(st_ + AH1_B + s_off) = H1_; \
        split8(bv0, bv1, H0_, H1_); \
        *(uint4*)(st_ + BH0_B + s_off) = H0_; \
        *(uint4*)(st_ + BH1_B + s_off) = H1_; \
    } while (0)

    LOADCHUNK(0);
    STORESTAGE(0);
    LOADCHUNK(1);
    __syncthreads();

    for (int kc = 0; kc < NCHUNK; kc++) {
        const char* st = smem + (kc & 1) * STAGE_B;

        uint32_t b0h[4], b1h[4], b0l[4], b1l[4];
#pragma unroll
        for (int nf = 0; nf < 4; nf++) {
            const int off = ((wn * 32 + nf * 8 + r) * SH + 2 * cq) * 2;
            b0h[nf] = *(const uint32_t*)(st + BH0_B + off);
            b1h[nf] = *(const uint32_t*)(st + BH0_B + off + 16);
            b0l[nf] = *(const uint32_t*)(st + BH1_B + off);
            b1l[nf] = *(const uint32_t*)(st + BH1_B + off + 16);
        }

#pragma unroll
        for (int mf = 0; mf < 4; mf++) {
            const int off0 = ((wm * 64 + mf * 16 + r) * SH + 2 * cq) * 2;
            const int off1 = off0 + 8 * SH * 2;
            uint32_t ah0 = *(const uint32_t*)(st + AH0_B + off0);
            uint32_t ah1 = *(const uint32_t*)(st + AH0_B + off1);
            uint32_t ah2 = *(const uint32_t*)(st + AH0_B + off0 + 16);
            uint32_t ah3 = *(const uint32_t*)(st + AH0_B + off1 + 16);
            uint32_t al0 = *(const uint32_t*)(st + AH1_B + off0);
            uint32_t al1 = *(const uint32_t*)(st + AH1_B + off1);
            uint32_t al2 = *(const uint32_t*)(st + AH1_B + off0 + 16);
            uint32_t al3 = *(const uint32_t*)(st + AH1_B + off1 + 16);
#pragma unroll
            for (int nf = 0; nf < 4; nf++) {
                mma16(acc[mf][nf], ah0, ah1, ah2, ah3, b0h[nf], b1h[nf]);  // h0*h0
                mma16(acc[mf][nf], ah0, ah1, ah2, ah3, b0l[nf], b1l[nf]);  // h0*h1
                mma16(acc[mf][nf], al0, al1, al2, al3, b0h[nf], b1h[nf]);  // h1*h0
            }
        }

        if (kc + 1 < NCHUNK) {
            STORESTAGE((kc + 1) & 1);
            if (kc + 2 < NCHUNK) LOADCHUNK(kc + 2);
        }
        __syncthreads();
    }

    // ---------------- epilogue: bias, square, per-row reduce, atomic ----------------
#pragma unroll
    for (int mf = 0; mf < 4; mf++) {
        float rs0 = 0.f, rs1 = 0.f;
#pragma unroll
        for (int nf = 0; nf < 4; nf++) {
            const int nc = wn * 32 + nf * 8 + 2 * cq;
            float b0 = sbias[nc], b1 = sbias[nc + 1];
            float v;
            v = acc[mf][nf][0] + b0; rs0 += v * v;
            v = acc[mf][nf][1] + b1; rs0 += v * v;
            v = acc[mf][nf][2] + b0; rs1 += v * v;
            v = acc[mf][nf][3] + b1; rs1 += v * v;
        }
        rs0 += __shfl_xor_sync(0xffffffffu, rs0, 1);
        rs0 += __shfl_xor_sync(0xffffffffu, rs0, 2);
        rs1 += __shfl_xor_sync(0xffffffffu, rs1, 1);
        rs1 += __shfl_xor_sync(0xffffffffu, rs1, 2);
        if (cq == 0) {
            const int mrow = row_off + m0 + wm * 64 + mf * 16 + r;
            atomicAdd(&g_sumsq[mrow],     rs0);
            atomicAdd(&g_sumsq[mrow + 8], rs1);
        }
    }
}

// ---------------- finalize ----------------
__global__ void finalize_kernel(const float* __restrict__ phi_scale,
                                const float* __restrict__ phi_bias,
                                float* __restrict__ out)
{
    const int b = blockIdx.x;
    const int tid = threadIdx.x;

    float lw = 0.f, lp = 0.f;
    for (int i = tid; i < 2048; i += 256)
        lw += sqrtf(g_sumsq[b * 2048 + i]);
#pragma unroll
    for (int h = 0; h < 4; h++) {
        int base = ROWS_WHOLE + h * ROWS_WHOLE + b * 2048;
        for (int i = tid; i < 2048; i += 256)
            lp += sqrtf(g_sumsq[base + i]);
    }

    __shared__ float sw[256];
    __shared__ float sp[256];
    sw[tid] = lw; sp[tid] = lp;
    __syncthreads();
    for (int s = 128; s > 0; s >>= 1) {
        if (tid < s) { sw[tid] += sw[tid + s]; sp[tid] += sp[tid + s]; }
        __syncthreads();
    }
    if (tid == 0) {
        float w = sw[0] / 2048.0f;
        float p = sp[0] / 8192.0f;
        float raw = (w - p) / (w + 1e-8f);
        float phi = phi_scale[0] * raw + phi_bias[0];
        out[b] = fminf(fmaxf(phi, 0.0f), 1.0f);
    }
}

extern "C" void kernel_launch(void* const* d_in, const int* in_sizes, int n_in,
                              void* d_out, int out_size)
{
    const float* cur  = (const float*)d_in[0];   // [4,2048,2048]
    const float* hist = (const float*)d_in[1];   // [4,4,2048,2048]
    const float* Ww   = (const float*)d_in[2];   // [1024,2048]
    const float* bw   = (const float*)d_in[3];   // [1024]
    const float* Wp   = (const float*)d_in[4];   // [1024,2048]
    const float* bp   = (const float*)d_in[5];   // [1024]
    const float* ps   = (const float*)d_in[6];
    const float* pb   = (const float*)d_in[7];
    float* out = (float*)d_out;                  // [4]

    cudaFuncSetAttribute(gemm_fp16x2_kernel,
                         cudaFuncAttributeMaxDynamicSharedMemorySize, SMEM_BYTES);

    zero_kernel<<<(ROWS_TOTAL + 255) / 256, 256>>>();

    gemm_fp16x2_kernel<<<dim3(N_DIM / BN, MB_TOTAL), 256, SMEM_BYTES>>>(
        cur, hist, Ww, bw, Wp, bp);

    finalize_kernel<<<4, 256>>>(ps, pb, out);
}